// round 8
// baseline (speedup 1.0000x reference)
#include <cuda_runtime.h>

#define B_   4
#define C_   64
#define H_   128
#define W_   128
#define O_   64
#define K2C  9
#define OFFC 18
#define HW   (H_*W_)

typedef unsigned long long ull;

__device__ float g_offset[B_ * OFFC * HW];   // [b][oc][h][w]
__device__ float g_wt[K2C * C_ * O_];        // [k2][c][o]

// ---- packed fp32x2 helpers (Blackwell) -------------------------------------
__device__ __forceinline__ void ffma2(ull& d, ull a, ull b) {
    asm("fma.rn.f32x2 %0, %1, %2, %0;" : "+l"(d) : "l"(a), "l"(b));
}
__device__ __forceinline__ ull pack2(float s) {
    ull r;
    asm("mov.b64 %0, {%1, %1};" : "=l"(r) : "f"(s));
    return r;
}
__device__ __forceinline__ float2 unpack2(ull v) {
    float2 f;
    asm("mov.b64 {%0, %1}, %2;" : "=f"(f.x), "=f"(f.y) : "l"(v));
    return f;
}

// ---------------------------------------------------------------------------
// Kernel 1: offset conv (3x3, 64 -> 18, pad 1).  (R5 logic, 3 blocks/SM)
// 256 threads = 64 pixel-pairs x 4 channel-chunks (16 ch each).
// Pixel-pair in LANE bits -> coalesced LDG.64; chunk in warp bits.
// ---------------------------------------------------------------------------
__global__ void __launch_bounds__(256, 3) offset_conv_kernel(
    const float* __restrict__ x,
    const float* __restrict__ w_off,
    const float* __restrict__ b_off)
{
    __shared__ float ws[C_ * K2C * 20];   // 45 KB [c][k][20 padded]
    __shared__ ull   red[3][9][128];      // 27 KB partials, indexed by pixel

    const int t = threadIdx.x;
    for (int i = t; i < C_ * K2C * 20; i += 256) {
        int rem = i % 20;
        int ck  = i / 20;
        float v = 0.f;
        if (rem < OFFC) {
            int c = ck / K2C, k = ck % K2C;
            v = w_off[(rem * C_ + c) * K2C + k];
        }
        ws[i] = v;
    }
    __syncthreads();

    const int pp    = t & 63;
    const int chunk = t >> 6;
    const int wo0   = pp * 2;
    const int ho    = blockIdx.x;
    const int b     = blockIdx.y;

    ull acc0[10], acc1[10];
#pragma unroll
    for (int i = 0; i < 10; i++) { acc0[i] = 0ull; acc1[i] = 0ull; }

    bool rv[3]; int rbase[3];
#pragma unroll
    for (int r = 0; r < 3; r++) {
        int yy = ho + r - 1;
        rv[r] = (yy >= 0) & (yy < H_);
        rbase[r] = yy * W_;
    }
    const bool s0v = (wo0 >= 2);
    const bool s2v = (wo0 <= W_ - 4);

    const float* xb = x + (size_t)b * C_ * HW;
    const int c0 = chunk * 16;
    for (int c = c0; c < c0 + 16; c++) {
        const float* xc = xb + c * HW;
        float f[3][6];
#pragma unroll
        for (int r = 0; r < 3; r++) {
            float2 a = make_float2(0.f, 0.f);
            float2 m = make_float2(0.f, 0.f);
            float2 e = make_float2(0.f, 0.f);
            if (rv[r]) {
                if (s0v) a = __ldg((const float2*)(xc + rbase[r] + wo0 - 2));
                m = __ldg((const float2*)(xc + rbase[r] + wo0));
                if (s2v) e = __ldg((const float2*)(xc + rbase[r] + wo0 + 2));
            }
            f[r][0] = a.x; f[r][1] = a.y;
            f[r][2] = m.x; f[r][3] = m.y;
            f[r][4] = e.x; f[r][5] = e.y;
        }
#pragma unroll
        for (int k = 0; k < K2C; k++) {
            int r = k / 3, kw = k % 3;
            ull s0 = pack2(f[r][1 + kw]);
            ull s1 = pack2(f[r][2 + kw]);
            const ulonglong2* wp = (const ulonglong2*)(ws + (c * K2C + k) * 20);
#pragma unroll
            for (int q = 0; q < 5; q++) {
                ulonglong2 w = wp[q];
                ffma2(acc0[2 * q + 0], s0, w.x);
                ffma2(acc0[2 * q + 1], s0, w.y);
                ffma2(acc1[2 * q + 0], s1, w.x);
                ffma2(acc1[2 * q + 1], s1, w.y);
            }
        }
    }

    if (chunk != 0) {
#pragma unroll
        for (int j = 0; j < 9; j++) {
            red[chunk - 1][j][wo0]     = acc0[j];
            red[chunk - 1][j][wo0 + 1] = acc1[j];
        }
    }
    __syncthreads();
    if (chunk == 0) {
        float* op = g_offset + ((size_t)(b * OFFC) * H_ + ho) * W_ + wo0;
#pragma unroll
        for (int j = 0; j < 9; j++) {
            float2 a0 = unpack2(acc0[j]);
            float2 a1 = unpack2(acc1[j]);
            float2 p10 = unpack2(red[0][j][wo0]);
            float2 p11 = unpack2(red[0][j][wo0 + 1]);
            float2 p20 = unpack2(red[1][j][wo0]);
            float2 p21 = unpack2(red[1][j][wo0 + 1]);
            float2 p30 = unpack2(red[2][j][wo0]);
            float2 p31 = unpack2(red[2][j][wo0 + 1]);
            float bx = __ldg(b_off + 2 * j + 0);
            float by = __ldg(b_off + 2 * j + 1);
            op[(size_t)(2 * j + 0) * HW]     = (a0.x + p10.x) + (p20.x + p30.x) + bx;
            op[(size_t)(2 * j + 0) * HW + 1] = (a1.x + p11.x) + (p21.x + p31.x) + bx;
            op[(size_t)(2 * j + 1) * HW]     = (a0.y + p10.y) + (p20.y + p30.y) + by;
            op[(size_t)(2 * j + 1) * HW + 1] = (a1.y + p11.y) + (p21.y + p31.y) + by;
        }
    }
}

// ---------------------------------------------------------------------------
// Kernel 2: transpose DCN weights [O][C][K2] -> [K2][C][O].
// ---------------------------------------------------------------------------
__global__ void transpose_w_kernel(const float* __restrict__ w_dcn)
{
    int i = blockIdx.x * 256 + threadIdx.x;
    if (i < O_ * C_ * K2C) {
        int o  = i / (C_ * K2C);
        int r  = i % (C_ * K2C);
        int c  = r / K2C;
        int k2 = r % K2C;
        g_wt[(k2 * C_ + c) * O_ + o] = w_dcn[i];
    }
}

// ---------------------------------------------------------------------------
// Kernel 3: deformable conv, pipelined, 1 ROW per block (grid 512),
// 3 blocks/SM. 256 threads.
// Sampling: warp (cg=warp&3 -> 8 ch, ph=warp>>2 -> 64-px half); thread covers
//   2 px x 8 ch, coalesced NCHW gathers, validity folded into weights.
// GEMM: thread tile = 8 contiguous px x 4 oc, f32x2 over pixel pairs.
//   Per channel: 2 LDS.128 (samples) + 1 LDS.128 (weights) + 4 pack2
//   -> 16 FFMA2.  acc = 16 ull = 32 regs (fits 85-reg/3-block budget).
// R5-style pipeline: next iteration's memory work issued before GEMM,
// one __syncthreads per iteration.
// ---------------------------------------------------------------------------
__global__ void __launch_bounds__(256, 3) deform_kernel(
    const float* __restrict__ x,
    const float* __restrict__ b_dcn,
    float* __restrict__ out)
{
    __shared__ float ws[2][C_ * O_];      // 32 KB, double-buffered per k2
    __shared__ float smp[2][32][132];     // 33.8 KB, double-buffered per half

    const int t    = threadIdx.x;
    const int lane = t & 31;
    const int warp = t >> 5;
    // sampling mapping
    const int s_cg = warp & 3;            // 8-channel group
    const int s_ph = warp >> 2;           // 64-px half
    // GEMM mapping
    const int ob     = (t & 15) * 4;      // 4 output channels
    const int pxbase = (t >> 4) * 8;      // 8 contiguous pixels
    const int ho   = blockIdx.x;
    const int b    = blockIdx.y;

    const float* xb = x + (size_t)b * C_ * HW;

    auto stage_ws = [&](int wbuf, int k2) {
        const float4* src = (const float4*)(g_wt + k2 * C_ * O_);
        float4* dst = (float4*)ws[wbuf];
#pragma unroll
        for (int q = 0; q < 4; q++)
            dst[t + q * 256] = src[t + q * 256];
    };

    auto sample = [&](int sbuf, int k2, int ch) {
#pragma unroll
        for (int i = 0; i < 2; i++) {
            int wo = 64 * s_ph + lane + 32 * i;
            const float* obp =
                g_offset + ((size_t)(b * OFFC + 2 * k2) * H_ + ho) * W_ + wo;
            float oy = __ldg(obp);
            float ox = __ldg(obp + HW);
            float py = (float)(ho - 1 + k2 / 3) + oy;
            float px = (float)(wo - 1 + k2 % 3) + ox;
            float y0f = floorf(py), x0f = floorf(px);
            float wy = py - y0f, wx = px - x0f;
            int y0 = (int)y0f, x0 = (int)x0f;
            float vy0 = ((y0 >= 0)  & (y0 < H_))     ? 1.f : 0.f;
            float vy1 = ((y0 >= -1) & (y0 < H_ - 1)) ? 1.f : 0.f;
            float vx0 = ((x0 >= 0)  & (x0 < W_))     ? 1.f : 0.f;
            float vx1 = ((x0 >= -1) & (x0 < W_ - 1)) ? 1.f : 0.f;
            float w00 = (1.f - wy) * (1.f - wx) * vy0 * vx0;
            float w01 = (1.f - wy) * wx         * vy0 * vx1;
            float w10 = wy * (1.f - wx)         * vy1 * vx0;
            float w11 = wy * wx                 * vy1 * vx1;
            int y0c = min(max(y0, 0), H_ - 1);
            int y1c = min(max(y0 + 1, 0), H_ - 1);
            int x0c = min(max(x0, 0), W_ - 1);
            int x1c = min(max(x0 + 1, 0), W_ - 1);
            int o00 = y0c * W_ + x0c;
            int o01 = y0c * W_ + x1c;
            int o10 = y1c * W_ + x0c;
            int o11 = y1c * W_ + x1c;
#pragma unroll
            for (int j = 0; j < 8; j++) {
                int cl = s_cg * 8 + j;
                const float* xc = xb + (ch * 32 + cl) * HW;
                float s = __ldg(xc + o00) * w00 + __ldg(xc + o01) * w01
                        + __ldg(xc + o10) * w10 + __ldg(xc + o11) * w11;
                smp[sbuf][cl][wo] = s;
            }
        }
    };

    ull acc[4][4];   // [px pair][oc]
#pragma unroll
    for (int i = 0; i < 4; i++)
#pragma unroll
        for (int j = 0; j < 4; j++) acc[i][j] = 0ull;

    stage_ws(0, 0);
    __syncthreads();
    sample(0, 0, 0);
    __syncthreads();

    for (int it = 0; it < 18; it++) {
        const int buf = it & 1;
        const int k2  = it >> 1;
        const int ch  = it & 1;

        // issue next iteration's memory work first (overlaps GEMM below)
        if (it < 17) {
            int nk2 = (it + 1) >> 1, nch = (it + 1) & 1;
            if (nch == 0) stage_ws(nk2 & 1, nk2);
            sample(buf ^ 1, nk2, nch);
        }

        // f32x2 GEMM (px-pair packed) over 32-channel half ch of tap k2
        {
            const float* wsl = ws[k2 & 1] + (ch * 32) * O_ + ob;
#pragma unroll 4
            for (int cl = 0; cl < 32; cl++) {
                float4 wv = *(const float4*)(wsl + cl * O_);
                ull w0 = pack2(wv.x), w1 = pack2(wv.y);
                ull w2 = pack2(wv.z), w3 = pack2(wv.w);
                const ulonglong2* srow =
                    (const ulonglong2*)(&smp[buf][cl][pxbase]);
                ulonglong2 sA = srow[0];
                ulonglong2 sB = srow[1];
                ffma2(acc[0][0], sA.x, w0); ffma2(acc[0][1], sA.x, w1);
                ffma2(acc[0][2], sA.x, w2); ffma2(acc[0][3], sA.x, w3);
                ffma2(acc[1][0], sA.y, w0); ffma2(acc[1][1], sA.y, w1);
                ffma2(acc[1][2], sA.y, w2); ffma2(acc[1][3], sA.y, w3);
                ffma2(acc[2][0], sB.x, w0); ffma2(acc[2][1], sB.x, w1);
                ffma2(acc[2][2], sB.x, w2); ffma2(acc[2][3], sB.x, w3);
                ffma2(acc[3][0], sB.y, w0); ffma2(acc[3][1], sB.y, w1);
                ffma2(acc[3][2], sB.y, w2); ffma2(acc[3][3], sB.y, w3);
            }
        }
        __syncthreads();
    }

    // epilogue: px pairs horizontally adjacent -> float2 stores
#pragma unroll
    for (int j = 0; j < 4; j++) {
        int o = ob + j;
        float bia = __ldg(b_dcn + o);
#pragma unroll
        for (int pp = 0; pp < 4; pp++) {
            int wo = pxbase + 2 * pp;
            float2 v = unpack2(acc[pp][j]);
            v.x += bia; v.y += bia;
            *(float2*)(&out[(((size_t)b * O_ + o) * H_ + ho) * W_ + wo]) = v;
        }
    }
}

// ---------------------------------------------------------------------------
extern "C" void kernel_launch(void* const* d_in, const int* in_sizes, int n_in,
                              void* d_out, int out_size)
{
    const float* x     = (const float*)d_in[0];
    const float* w_off = (const float*)d_in[1];
    const float* b_off = (const float*)d_in[2];
    const float* w_dcn = (const float*)d_in[3];
    const float* b_dcn = (const float*)d_in[4];
    float* out = (float*)d_out;

    transpose_w_kernel<<<(O_ * C_ * K2C + 255) / 256, 256>>>(w_dcn);
    offset_conv_kernel<<<dim3(H_, B_), 256>>>(x, w_off, b_off);
    deform_kernel<<<dim3(H_, B_), 256>>>(x, b_dcn, out);
}

// round 9
// speedup vs baseline: 2.2302x; 2.2302x over previous
#include <cuda_runtime.h>
#include <cuda_bf16.h>
#include <cstdint>

#define B_   4
#define C_   64
#define H_   128
#define W_   128
#define O_   64
#define K2C  9
#define OFFC 18
#define HW   (H_*W_)

typedef unsigned long long ull;

__device__ float g_offset[B_ * OFFC * HW];                   // [b][oc][h][w]
__device__ __align__(16) uint32_t g_wq_hi[K2C * 4 * O_ * 8]; // [k2][q][o][cp] bf16x2
__device__ __align__(16) uint32_t g_wq_lo[K2C * 4 * O_ * 8];

// ---- packed fp32x2 helpers (Blackwell) -------------------------------------
__device__ __forceinline__ void ffma2(ull& d, ull a, ull b) {
    asm("fma.rn.f32x2 %0, %1, %2, %0;" : "+l"(d) : "l"(a), "l"(b));
}
__device__ __forceinline__ ull pack2(float s) {
    ull r;
    asm("mov.b64 %0, {%1, %1};" : "=l"(r) : "f"(s));
    return r;
}
__device__ __forceinline__ float2 unpack2(ull v) {
    float2 f;
    asm("mov.b64 {%0, %1}, %2;" : "=f"(f.x), "=f"(f.y) : "l"(v));
    return f;
}

// ---- bf16 warp MMA (m16n8k16, fp32 accum) ----------------------------------
__device__ __forceinline__ void mma_bf16(float* d, const uint32_t* a,
                                         const uint32_t* b) {
    asm volatile(
        "mma.sync.aligned.m16n8k16.row.col.f32.bf16.bf16.f32 "
        "{%0,%1,%2,%3}, {%4,%5,%6,%7}, {%8,%9}, {%0,%1,%2,%3};"
        : "+f"(d[0]), "+f"(d[1]), "+f"(d[2]), "+f"(d[3])
        : "r"(a[0]), "r"(a[1]), "r"(a[2]), "r"(a[3]),
          "r"(b[0]), "r"(b[1]));
}

// ---------------------------------------------------------------------------
// Kernel 1: offset conv (3x3, 64 -> 18, pad 1). Verbatim R5 (proven 55 us).
// ---------------------------------------------------------------------------
__global__ void __launch_bounds__(256, 2) offset_conv_kernel(
    const float* __restrict__ x,
    const float* __restrict__ w_off,
    const float* __restrict__ b_off)
{
    __shared__ float ws[C_ * K2C * 20];
    __shared__ ull   red[3][9][128];

    const int t = threadIdx.x;
    for (int i = t; i < C_ * K2C * 20; i += 256) {
        int rem = i % 20;
        int ck  = i / 20;
        float v = 0.f;
        if (rem < OFFC) {
            int c = ck / K2C, k = ck % K2C;
            v = w_off[(rem * C_ + c) * K2C + k];
        }
        ws[i] = v;
    }
    __syncthreads();

    const int pp    = t & 63;
    const int chunk = t >> 6;
    const int wo0   = pp * 2;
    const int ho    = blockIdx.x;
    const int b     = blockIdx.y;

    ull acc0[10], acc1[10];
#pragma unroll
    for (int i = 0; i < 10; i++) { acc0[i] = 0ull; acc1[i] = 0ull; }

    bool rv[3]; int rbase[3];
#pragma unroll
    for (int r = 0; r < 3; r++) {
        int yy = ho + r - 1;
        rv[r] = (yy >= 0) & (yy < H_);
        rbase[r] = yy * W_;
    }
    const bool s0v = (wo0 >= 2);
    const bool s2v = (wo0 <= W_ - 4);

    const float* xb = x + (size_t)b * C_ * HW;
    const int c0 = chunk * 16;
    for (int c = c0; c < c0 + 16; c++) {
        const float* xc = xb + c * HW;
        float f[3][6];
#pragma unroll
        for (int r = 0; r < 3; r++) {
            float2 a = make_float2(0.f, 0.f);
            float2 m = make_float2(0.f, 0.f);
            float2 e = make_float2(0.f, 0.f);
            if (rv[r]) {
                if (s0v) a = __ldg((const float2*)(xc + rbase[r] + wo0 - 2));
                m = __ldg((const float2*)(xc + rbase[r] + wo0));
                if (s2v) e = __ldg((const float2*)(xc + rbase[r] + wo0 + 2));
            }
            f[r][0] = a.x; f[r][1] = a.y;
            f[r][2] = m.x; f[r][3] = m.y;
            f[r][4] = e.x; f[r][5] = e.y;
        }
#pragma unroll
        for (int k = 0; k < K2C; k++) {
            int r = k / 3, kw = k % 3;
            ull s0 = pack2(f[r][1 + kw]);
            ull s1 = pack2(f[r][2 + kw]);
            const ulonglong2* wp = (const ulonglong2*)(ws + (c * K2C + k) * 20);
#pragma unroll
            for (int q = 0; q < 5; q++) {
                ulonglong2 w = wp[q];
                ffma2(acc0[2 * q + 0], s0, w.x);
                ffma2(acc0[2 * q + 1], s0, w.y);
                ffma2(acc1[2 * q + 0], s1, w.x);
                ffma2(acc1[2 * q + 1], s1, w.y);
            }
        }
    }

    if (chunk != 0) {
#pragma unroll
        for (int j = 0; j < 9; j++) {
            red[chunk - 1][j][wo0]     = acc0[j];
            red[chunk - 1][j][wo0 + 1] = acc1[j];
        }
    }
    __syncthreads();
    if (chunk == 0) {
        float* op = g_offset + ((size_t)(b * OFFC) * H_ + ho) * W_ + wo0;
#pragma unroll
        for (int j = 0; j < 9; j++) {
            float2 a0 = unpack2(acc0[j]);
            float2 a1 = unpack2(acc1[j]);
            float2 p10 = unpack2(red[0][j][wo0]);
            float2 p11 = unpack2(red[0][j][wo0 + 1]);
            float2 p20 = unpack2(red[1][j][wo0]);
            float2 p21 = unpack2(red[1][j][wo0 + 1]);
            float2 p30 = unpack2(red[2][j][wo0]);
            float2 p31 = unpack2(red[2][j][wo0 + 1]);
            float bx = __ldg(b_off + 2 * j + 0);
            float by = __ldg(b_off + 2 * j + 1);
            op[(size_t)(2 * j + 0) * HW]     = (a0.x + p10.x) + (p20.x + p30.x) + bx;
            op[(size_t)(2 * j + 0) * HW + 1] = (a1.x + p11.x) + (p21.x + p31.x) + bx;
            op[(size_t)(2 * j + 1) * HW]     = (a0.y + p10.y) + (p20.y + p30.y) + by;
            op[(size_t)(2 * j + 1) * HW + 1] = (a1.y + p11.y) + (p21.y + p31.y) + by;
        }
    }
}

// ---------------------------------------------------------------------------
// Kernel 2: split DCN weights into bf16 hi/lo, packed as [k2][q][o][ch-pair].
// w = hi + lo with hi = bf16(w), lo = bf16(w - hi).
// ---------------------------------------------------------------------------
__global__ void prep_w_kernel(const float* __restrict__ w_dcn)
{
    int i = blockIdx.x * 256 + threadIdx.x;
    if (i >= K2C * 4 * O_ * 8) return;
    int k2 = i / (4 * O_ * 8);
    int r  = i % (4 * O_ * 8);
    int q  = r / (O_ * 8);
    int r2 = r % (O_ * 8);
    int o  = r2 / 8;
    int cp = r2 % 8;
    int c  = q * 16 + cp * 2;

    float w0 = w_dcn[(o * C_ + c) * K2C + k2];
    float w1 = w_dcn[(o * C_ + c + 1) * K2C + k2];

    __nv_bfloat16 h0 = __float2bfloat16_rn(w0);
    __nv_bfloat16 h1 = __float2bfloat16_rn(w1);
    __nv_bfloat16 l0 = __float2bfloat16_rn(w0 - __bfloat162float(h0));
    __nv_bfloat16 l1 = __float2bfloat16_rn(w1 - __bfloat162float(h1));

    __nv_bfloat162 hh; hh.x = h0; hh.y = h1;
    __nv_bfloat162 ll; ll.x = l0; ll.y = l1;
    g_wq_hi[i] = *reinterpret_cast<uint32_t*>(&hh);
    g_wq_lo[i] = *reinterpret_cast<uint32_t*>(&ll);
}

// ---------------------------------------------------------------------------
// Kernel 3: deformable conv — R5 pipeline skeleton, tensor-core GEMM.
// Block = 256 px (2 rows), 256 threads, 36 iterations (9 taps x 4 ch-quarters
// of 16 channels). Per iteration: sample next quarter (bf16 hi/lo pairs into
// smp) + stage next weight quarter, then 3-split bf16 MMA on current buffers.
// Warp GEMM tile: 4 px-tiles (64 px) x 4 oc-tiles (32 oc), acc = 64 fp32.
// ---------------------------------------------------------------------------
__global__ void __launch_bounds__(256, 2) deform_kernel(
    const float* __restrict__ x,
    const float* __restrict__ b_dcn,
    float* __restrict__ out)
{
    __shared__ __align__(16) uint32_t smp[2][2][256][9];  // [buf][hi/lo][px][chpair+pad]
    __shared__ __align__(16) uint32_t wsm[2][2][O_][10];  // [buf][hi/lo][o][chpair+pad]

    const int t    = threadIdx.x;
    const int lane = t & 31;
    const int warp = t >> 5;
    // sampling map: warp -> (64-px group, 8-ch subgroup of the 16-ch quarter)
    const int s_pxg = warp >> 1;
    const int s_cg  = warp & 1;
    // GEMM map: warp -> (64-px group, 32-oc group)
    const int g_px0 = 64 * (warp >> 1);
    const int g_ob  = 32 * (warp & 1);
    const int ho0   = blockIdx.x * 2;
    const int b     = blockIdx.y;

    const float* xb = x + (size_t)b * C_ * HW;

    auto stage_ws = [&](int buf, int tap, int q) {
        const uint2* srch = (const uint2*)(g_wq_hi + (size_t)((tap * 4 + q) * O_ * 8));
        const uint2* srcl = (const uint2*)(g_wq_lo + (size_t)((tap * 4 + q) * O_ * 8));
        int o = t >> 2, s = t & 3;
        uint2 vh = __ldg(srch + o * 4 + s);
        uint2 vl = __ldg(srcl + o * 4 + s);
        *(uint2*)&wsm[buf][0][o][2 * s] = vh;
        *(uint2*)&wsm[buf][1][o][2 * s] = vl;
    };

    auto sample = [&](int buf, int tap, int q) {
        const int cbase = q * 16 + s_cg * 8;
#pragma unroll
        for (int i = 0; i < 2; i++) {
            int p  = 64 * s_pxg + lane + 32 * i;
            int ho = ho0 + (p >> 7);
            int wo = p & 127;
            const float* obp =
                g_offset + ((size_t)(b * OFFC + 2 * tap) * H_ + ho) * W_ + wo;
            float oy = __ldg(obp);
            float ox = __ldg(obp + HW);
            float py = (float)(ho - 1 + tap / 3) + oy;
            float px = (float)(wo - 1 + tap % 3) + ox;
            float y0f = floorf(py), x0f = floorf(px);
            float wy = py - y0f, wx = px - x0f;
            int y0 = (int)y0f, x0 = (int)x0f;
            float vy0 = ((y0 >= 0)  & (y0 < H_))     ? 1.f : 0.f;
            float vy1 = ((y0 >= -1) & (y0 < H_ - 1)) ? 1.f : 0.f;
            float vx0 = ((x0 >= 0)  & (x0 < W_))     ? 1.f : 0.f;
            float vx1 = ((x0 >= -1) & (x0 < W_ - 1)) ? 1.f : 0.f;
            float w00 = (1.f - wy) * (1.f - wx) * vy0 * vx0;
            float w01 = (1.f - wy) * wx         * vy0 * vx1;
            float w10 = wy * (1.f - wx)         * vy1 * vx0;
            float w11 = wy * wx                 * vy1 * vx1;
            int y0c = min(max(y0, 0), H_ - 1);
            int y1c = min(max(y0 + 1, 0), H_ - 1);
            int x0c = min(max(x0, 0), W_ - 1);
            int x1c = min(max(x0 + 1, 0), W_ - 1);
            int o00 = y0c * W_ + x0c;
            int o01 = y0c * W_ + x1c;
            int o10 = y1c * W_ + x0c;
            int o11 = y1c * W_ + x1c;
#pragma unroll
            for (int pr = 0; pr < 4; pr++) {
                int c0 = cbase + 2 * pr;
                const float* xc0 = xb + c0 * HW;
                const float* xc1 = xc0 + HW;
                float s0 = __ldg(xc0 + o00) * w00 + __ldg(xc0 + o01) * w01
                         + __ldg(xc0 + o10) * w10 + __ldg(xc0 + o11) * w11;
                float s1 = __ldg(xc1 + o00) * w00 + __ldg(xc1 + o01) * w01
                         + __ldg(xc1 + o10) * w10 + __ldg(xc1 + o11) * w11;
                float2 sv = make_float2(s0, s1);
                __nv_bfloat162 h2 = __float22bfloat162_rn(sv);
                float2 hv = make_float2(__bfloat162float(h2.x),
                                        __bfloat162float(h2.y));
                __nv_bfloat162 l2 =
                    __float22bfloat162_rn(make_float2(sv.x - hv.x, sv.y - hv.y));
                smp[buf][0][p][s_cg * 4 + pr] = *reinterpret_cast<uint32_t*>(&h2);
                smp[buf][1][p][s_cg * 4 + pr] = *reinterpret_cast<uint32_t*>(&l2);
            }
        }
    };

    float acc[4][4][4];
#pragma unroll
    for (int i = 0; i < 4; i++)
#pragma unroll
        for (int j = 0; j < 4; j++)
#pragma unroll
            for (int k = 0; k < 4; k++) acc[i][j][k] = 0.f;

    // prologue
    stage_ws(0, 0, 0);
    sample(0, 0, 0);
    __syncthreads();

    const int g  = lane >> 2;
    const int tt = lane & 3;

    for (int it = 0; it < 36; it++) {
        const int buf = it & 1;

        if (it < 35) {
            int n = it + 1;
            stage_ws(n & 1, n >> 2, n & 3);
            sample(n & 1, n >> 2, n & 3);
        }

        // ---- 3-split bf16 MMA over this 16-channel quarter ----
        {
            const uint32_t (*sh)[9]  = smp[buf][0];
            const uint32_t (*sl)[9]  = smp[buf][1];
            const uint32_t (*wh)[10] = wsm[buf][0];
            const uint32_t (*wl)[10] = wsm[buf][1];

            uint32_t bh[4][2], bl[4][2];
#pragma unroll
            for (int oct = 0; oct < 4; oct++) {
                int orow = g_ob + oct * 8 + g;
                bh[oct][0] = wh[orow][tt];
                bh[oct][1] = wh[orow][tt + 4];
                bl[oct][0] = wl[orow][tt];
                bl[oct][1] = wl[orow][tt + 4];
            }
#pragma unroll
            for (int pxt = 0; pxt < 4; pxt++) {
                int r0 = g_px0 + pxt * 16 + g;
                int r1 = r0 + 8;
                uint32_t ah[4] = { sh[r0][tt], sh[r1][tt],
                                   sh[r0][tt + 4], sh[r1][tt + 4] };
                uint32_t al[4] = { sl[r0][tt], sl[r1][tt],
                                   sl[r0][tt + 4], sl[r1][tt + 4] };
#pragma unroll
                for (int oct = 0; oct < 4; oct++) {
                    mma_bf16(acc[pxt][oct], ah, bh[oct]);
                    mma_bf16(acc[pxt][oct], ah, bl[oct]);
                    mma_bf16(acc[pxt][oct], al, bh[oct]);
                }
            }
        }
        __syncthreads();
    }

    // ---- epilogue: D-fragment scatter + bias ----
#pragma unroll
    for (int oct = 0; oct < 4; oct++) {
        int oc0 = g_ob + oct * 8 + 2 * tt;
        float bia0 = __ldg(b_dcn + oc0);
        float bia1 = __ldg(b_dcn + oc0 + 1);
#pragma unroll
        for (int pxt = 0; pxt < 4; pxt++) {
            int p0 = g_px0 + pxt * 16 + g;   // rows g and g+8
#pragma unroll
            for (int rr = 0; rr < 2; rr++) {
                int p  = p0 + 8 * rr;
                int ho = ho0 + (p >> 7);
                int wo = p & 127;
                float d0 = acc[pxt][oct][2 * rr + 0] + bia0;
                float d1 = acc[pxt][oct][2 * rr + 1] + bia1;
                out[(((size_t)b * O_ + oc0)     * H_ + ho) * W_ + wo] = d0;
                out[(((size_t)b * O_ + oc0 + 1) * H_ + ho) * W_ + wo] = d1;
            }
        }
    }
}

// ---------------------------------------------------------------------------
extern "C" void kernel_launch(void* const* d_in, const int* in_sizes, int n_in,
                              void* d_out, int out_size)
{
    const float* x     = (const float*)d_in[0];
    const float* w_off = (const float*)d_in[1];
    const float* b_off = (const float*)d_in[2];
    const float* w_dcn = (const float*)d_in[3];
    const float* b_dcn = (const float*)d_in[4];
    float* out = (float*)d_out;

    prep_w_kernel<<<(K2C * 4 * O_ * 8 + 255) / 256, 256>>>(w_dcn);
    offset_conv_kernel<<<dim3(H_, B_), 256>>>(x, w_off, b_off);
    deform_kernel<<<dim3(H_ / 2, B_), 256>>>(x, b_dcn, out);
}

// round 10
// speedup vs baseline: 2.3734x; 1.0642x over previous
#include <cuda_runtime.h>
#include <cuda_bf16.h>
#include <cstdint>

#define B_   4
#define C_   64
#define H_   128
#define W_   128
#define O_   64
#define K2C  9
#define OFFC 18
#define NOFF 24   // padded offset-channel count for MMA
#define HW   (H_*W_)

__device__ float g_offset[B_ * OFFC * HW];                    // [b][oc][h][w]
__device__ __align__(16) uint32_t g_wq_hi[K2C * 4 * O_ * 8];  // dcn w [k2][q][o][cp]
__device__ __align__(16) uint32_t g_wq_lo[K2C * 4 * O_ * 8];
__device__ __align__(16) uint32_t g_wo_hi[K2C * 4 * NOFF * 8];// off w [k2][q][o][cp]
__device__ __align__(16) uint32_t g_wo_lo[K2C * 4 * NOFF * 8];

// ---- bf16 warp MMA (m16n8k16, fp32 accum) ----------------------------------
__device__ __forceinline__ void mma_bf16(float* d, const uint32_t* a,
                                         const uint32_t* b) {
    asm volatile(
        "mma.sync.aligned.m16n8k16.row.col.f32.bf16.bf16.f32 "
        "{%0,%1,%2,%3}, {%4,%5,%6,%7}, {%8,%9}, {%0,%1,%2,%3};"
        : "+f"(d[0]), "+f"(d[1]), "+f"(d[2]), "+f"(d[3])
        : "r"(a[0]), "r"(a[1]), "r"(a[2]), "r"(a[3]),
          "r"(b[0]), "r"(b[1]));
}

__device__ __forceinline__ void split_store(uint32_t* hi, uint32_t* lo,
                                            float s0, float s1) {
    float2 sv = make_float2(s0, s1);
    __nv_bfloat162 h2 = __float22bfloat162_rn(sv);
    float2 hv = make_float2(__bfloat162float(h2.x), __bfloat162float(h2.y));
    __nv_bfloat162 l2 = __float22bfloat162_rn(make_float2(sv.x - hv.x, sv.y - hv.y));
    *hi = *reinterpret_cast<uint32_t*>(&h2);
    *lo = *reinterpret_cast<uint32_t*>(&l2);
}

// ---------------------------------------------------------------------------
// Kernel 1: prep both weight tensors (bf16 hi/lo split, [k2][q][o][chpair]).
// ---------------------------------------------------------------------------
#define NDCN (K2C * 4 * O_ * 8)
#define NOFFW (K2C * 4 * NOFF * 8)

__global__ void prep_w_kernel(const float* __restrict__ w_dcn,
                              const float* __restrict__ w_off)
{
    int i = blockIdx.x * 256 + threadIdx.x;
    if (i < NDCN) {
        int k2 = i / (4 * O_ * 8);
        int r  = i % (4 * O_ * 8);
        int q  = r / (O_ * 8);
        int r2 = r % (O_ * 8);
        int o  = r2 / 8;
        int cp = r2 % 8;
        int c  = q * 16 + cp * 2;
        float w0 = w_dcn[(o * C_ + c) * K2C + k2];
        float w1 = w_dcn[(o * C_ + c + 1) * K2C + k2];
        split_store(&g_wq_hi[i], &g_wq_lo[i], w0, w1);
    } else {
        int j = i - NDCN;
        if (j < NOFFW) {
            int k2 = j / (4 * NOFF * 8);
            int r  = j % (4 * NOFF * 8);
            int q  = r / (NOFF * 8);
            int r2 = r % (NOFF * 8);
            int o  = r2 / 8;
            int cp = r2 % 8;
            int c  = q * 16 + cp * 2;
            float w0 = 0.f, w1 = 0.f;
            if (o < OFFC) {
                w0 = w_off[(o * C_ + c) * K2C + k2];
                w1 = w_off[(o * C_ + c + 1) * K2C + k2];
            }
            split_store(&g_wo_hi[j], &g_wo_lo[j], w0, w1);
        }
    }
}

// ---------------------------------------------------------------------------
// Kernel 2: offset conv (3x3, 64 -> 18, pad 1) as 3-split bf16 implicit GEMM.
// Same skeleton as deform: 256 px (2 rows) per block, 36 iterations
// (9 taps x 4 ch-quarters). A-staging is ONE aligned coalesced load per
// (px, ch) with boundary zeroing. Warp GEMM tile: 32 px x 24 oc
// (2 px-tiles x 3 oc-tiles x 3 splits = 18 MMAs per warp-iter).
// ---------------------------------------------------------------------------
__global__ void __launch_bounds__(256, 2) offset_conv_kernel(
    const float* __restrict__ x,
    const float* __restrict__ b_off)
{
    __shared__ __align__(16) uint32_t smp[2][2][256][9];   // 73.7 KB
    __shared__ __align__(16) uint32_t wsm[2][2][NOFF][10]; // 3.84 KB

    const int t    = threadIdx.x;
    const int lane = t & 31;
    const int warp = t >> 5;
    const int s_pxg = warp >> 1;          // 64-px group (sampling)
    const int s_cg  = warp & 1;           // 8-ch subgroup (sampling)
    const int px0   = warp * 32;          // GEMM: 32 px per warp
    const int ho0   = blockIdx.x * 2;
    const int b     = blockIdx.y;

    const float* xb = x + (size_t)b * C_ * HW;

    auto stage_ws = [&](int buf, int tap, int q) {
        if (t < 192) {
            int h = t >= 96;
            int r = t - h * 96;
            int o = r >> 2, s = r & 3;
            const uint2* src = (const uint2*)((h ? g_wo_lo : g_wo_hi)
                               + (size_t)((tap * 4 + q) * NOFF * 8));
            uint2 v = __ldg(src + o * 4 + s);
            *(uint2*)&wsm[buf][h][o][2 * s] = v;
        }
    };

    auto sample = [&](int buf, int tap, int q) {
        const int dy = tap / 3 - 1, dx = tap % 3 - 1;
        const int cbase = q * 16 + s_cg * 8;
#pragma unroll
        for (int i = 0; i < 2; i++) {
            int p  = 64 * s_pxg + lane + 32 * i;
            int ho = ho0 + (p >> 7);
            int wo = p & 127;
            int yy = ho + dy, xx = wo + dx;
            bool v = (yy >= 0) & (yy < H_) & (xx >= 0) & (xx < W_);
            int off = yy * W_ + xx;
#pragma unroll
            for (int pr = 0; pr < 4; pr++) {
                int c0 = cbase + 2 * pr;
                float s0 = v ? __ldg(xb + (size_t)c0 * HW + off) : 0.f;
                float s1 = v ? __ldg(xb + (size_t)(c0 + 1) * HW + off) : 0.f;
                split_store(&smp[buf][0][p][s_cg * 4 + pr],
                            &smp[buf][1][p][s_cg * 4 + pr], s0, s1);
            }
        }
    };

    float acc[2][3][4];
#pragma unroll
    for (int i = 0; i < 2; i++)
#pragma unroll
        for (int j = 0; j < 3; j++)
#pragma unroll
            for (int k = 0; k < 4; k++) acc[i][j][k] = 0.f;

    stage_ws(0, 0, 0);
    sample(0, 0, 0);
    __syncthreads();

    const int g  = lane >> 2;
    const int tt = lane & 3;

    for (int it = 0; it < 36; it++) {
        const int buf = it & 1;
        if (it < 35) {
            int n = it + 1;
            stage_ws(n & 1, n >> 2, n & 3);
            sample(n & 1, n >> 2, n & 3);
        }
        {
            const uint32_t (*sh)[9]  = smp[buf][0];
            const uint32_t (*sl)[9]  = smp[buf][1];
            const uint32_t (*wh)[10] = wsm[buf][0];
            const uint32_t (*wl)[10] = wsm[buf][1];

            uint32_t bh[3][2], bl[3][2];
#pragma unroll
            for (int oct = 0; oct < 3; oct++) {
                int orow = oct * 8 + g;
                bh[oct][0] = wh[orow][tt];
                bh[oct][1] = wh[orow][tt + 4];
                bl[oct][0] = wl[orow][tt];
                bl[oct][1] = wl[orow][tt + 4];
            }
#pragma unroll
            for (int pxt = 0; pxt < 2; pxt++) {
                int r0 = px0 + pxt * 16 + g;
                int r1 = r0 + 8;
                uint32_t ah[4] = { sh[r0][tt], sh[r1][tt],
                                   sh[r0][tt + 4], sh[r1][tt + 4] };
                uint32_t al[4] = { sl[r0][tt], sl[r1][tt],
                                   sl[r0][tt + 4], sl[r1][tt + 4] };
#pragma unroll
                for (int oct = 0; oct < 3; oct++) {
                    mma_bf16(acc[pxt][oct], ah, bh[oct]);
                    mma_bf16(acc[pxt][oct], ah, bl[oct]);
                    mma_bf16(acc[pxt][oct], al, bh[oct]);
                }
            }
        }
        __syncthreads();
    }

    // epilogue: scatter D fragments (skip padded oc >= 18)
#pragma unroll
    for (int oct = 0; oct < 3; oct++) {
        int oc0 = oct * 8 + 2 * tt;
        if (oc0 < OFFC) {
            float bia0 = __ldg(b_off + oc0);
            float bia1 = (oc0 + 1 < OFFC) ? __ldg(b_off + oc0 + 1) : 0.f;
#pragma unroll
            for (int pxt = 0; pxt < 2; pxt++) {
#pragma unroll
                for (int rr = 0; rr < 2; rr++) {
                    int p  = px0 + pxt * 16 + g + 8 * rr;
                    int ho = ho0 + (p >> 7);
                    int wo = p & 127;
                    g_offset[((size_t)(b * OFFC + oc0) * H_ + ho) * W_ + wo] =
                        acc[pxt][oct][2 * rr + 0] + bia0;
                    if (oc0 + 1 < OFFC)
                        g_offset[((size_t)(b * OFFC + oc0 + 1) * H_ + ho) * W_ + wo] =
                            acc[pxt][oct][2 * rr + 1] + bia1;
                }
            }
        }
    }
}

// ---------------------------------------------------------------------------
// Kernel 3: deformable conv — unchanged from R9 (proven).
// ---------------------------------------------------------------------------
__global__ void __launch_bounds__(256, 2) deform_kernel(
    const float* __restrict__ x,
    const float* __restrict__ b_dcn,
    float* __restrict__ out)
{
    __shared__ __align__(16) uint32_t smp[2][2][256][9];
    __shared__ __align__(16) uint32_t wsm[2][2][O_][10];

    const int t    = threadIdx.x;
    const int lane = t & 31;
    const int warp = t >> 5;
    const int s_pxg = warp >> 1;
    const int s_cg  = warp & 1;
    const int g_px0 = 64 * (warp >> 1);
    const int g_ob  = 32 * (warp & 1);
    const int ho0   = blockIdx.x * 2;
    const int b     = blockIdx.y;

    const float* xb = x + (size_t)b * C_ * HW;

    auto stage_ws = [&](int buf, int tap, int q) {
        const uint2* srch = (const uint2*)(g_wq_hi + (size_t)((tap * 4 + q) * O_ * 8));
        const uint2* srcl = (const uint2*)(g_wq_lo + (size_t)((tap * 4 + q) * O_ * 8));
        int o = t >> 2, s = t & 3;
        uint2 vh = __ldg(srch + o * 4 + s);
        uint2 vl = __ldg(srcl + o * 4 + s);
        *(uint2*)&wsm[buf][0][o][2 * s] = vh;
        *(uint2*)&wsm[buf][1][o][2 * s] = vl;
    };

    auto sample = [&](int buf, int tap, int q) {
        const int cbase = q * 16 + s_cg * 8;
#pragma unroll
        for (int i = 0; i < 2; i++) {
            int p  = 64 * s_pxg + lane + 32 * i;
            int ho = ho0 + (p >> 7);
            int wo = p & 127;
            const float* obp =
                g_offset + ((size_t)(b * OFFC + 2 * tap) * H_ + ho) * W_ + wo;
            float oy = __ldg(obp);
            float ox = __ldg(obp + HW);
            float py = (float)(ho - 1 + tap / 3) + oy;
            float px = (float)(wo - 1 + tap % 3) + ox;
            float y0f = floorf(py), x0f = floorf(px);
            float wy = py - y0f, wx = px - x0f;
            int y0 = (int)y0f, x0 = (int)x0f;
            float vy0 = ((y0 >= 0)  & (y0 < H_))     ? 1.f : 0.f;
            float vy1 = ((y0 >= -1) & (y0 < H_ - 1)) ? 1.f : 0.f;
            float vx0 = ((x0 >= 0)  & (x0 < W_))     ? 1.f : 0.f;
            float vx1 = ((x0 >= -1) & (x0 < W_ - 1)) ? 1.f : 0.f;
            float w00 = (1.f - wy) * (1.f - wx) * vy0 * vx0;
            float w01 = (1.f - wy) * wx         * vy0 * vx1;
            float w10 = wy * (1.f - wx)         * vy1 * vx0;
            float w11 = wy * wx                 * vy1 * vx1;
            int y0c = min(max(y0, 0), H_ - 1);
            int y1c = min(max(y0 + 1, 0), H_ - 1);
            int x0c = min(max(x0, 0), W_ - 1);
            int x1c = min(max(x0 + 1, 0), W_ - 1);
            int o00 = y0c * W_ + x0c;
            int o01 = y0c * W_ + x1c;
            int o10 = y1c * W_ + x0c;
            int o11 = y1c * W_ + x1c;
#pragma unroll
            for (int pr = 0; pr < 4; pr++) {
                int c0 = cbase + 2 * pr;
                const float* xc0 = xb + c0 * HW;
                const float* xc1 = xc0 + HW;
                float s0 = __ldg(xc0 + o00) * w00 + __ldg(xc0 + o01) * w01
                         + __ldg(xc0 + o10) * w10 + __ldg(xc0 + o11) * w11;
                float s1 = __ldg(xc1 + o00) * w00 + __ldg(xc1 + o01) * w01
                         + __ldg(xc1 + o10) * w10 + __ldg(xc1 + o11) * w11;
                split_store(&smp[buf][0][p][s_cg * 4 + pr],
                            &smp[buf][1][p][s_cg * 4 + pr], s0, s1);
            }
        }
    };

    float acc[4][4][4];
#pragma unroll
    for (int i = 0; i < 4; i++)
#pragma unroll
        for (int j = 0; j < 4; j++)
#pragma unroll
            for (int k = 0; k < 4; k++) acc[i][j][k] = 0.f;

    stage_ws(0, 0, 0);
    sample(0, 0, 0);
    __syncthreads();

    const int g  = lane >> 2;
    const int tt = lane & 3;

    for (int it = 0; it < 36; it++) {
        const int buf = it & 1;
        if (it < 35) {
            int n = it + 1;
            stage_ws(n & 1, n >> 2, n & 3);
            sample(n & 1, n >> 2, n & 3);
        }
        {
            const uint32_t (*sh)[9]  = smp[buf][0];
            const uint32_t (*sl)[9]  = smp[buf][1];
            const uint32_t (*wh)[10] = wsm[buf][0];
            const uint32_t (*wl)[10] = wsm[buf][1];

            uint32_t bh[4][2], bl[4][2];
#pragma unroll
            for (int oct = 0; oct < 4; oct++) {
                int orow = g_ob + oct * 8 + g;
                bh[oct][0] = wh[orow][tt];
                bh[oct][1] = wh[orow][tt + 4];
                bl[oct][0] = wl[orow][tt];
                bl[oct][1] = wl[orow][tt + 4];
            }
#pragma unroll
            for (int pxt = 0; pxt < 4; pxt++) {
                int r0 = g_px0 + pxt * 16 + g;
                int r1 = r0 + 8;
                uint32_t ah[4] = { sh[r0][tt], sh[r1][tt],
                                   sh[r0][tt + 4], sh[r1][tt + 4] };
                uint32_t al[4] = { sl[r0][tt], sl[r1][tt],
                                   sl[r0][tt + 4], sl[r1][tt + 4] };
#pragma unroll
                for (int oct = 0; oct < 4; oct++) {
                    mma_bf16(acc[pxt][oct], ah, bh[oct]);
                    mma_bf16(acc[pxt][oct], ah, bl[oct]);
                    mma_bf16(acc[pxt][oct], al, bh[oct]);
                }
            }
        }
        __syncthreads();
    }

#pragma unroll
    for (int oct = 0; oct < 4; oct++) {
        int oc0 = g_ob + oct * 8 + 2 * tt;
        float bia0 = __ldg(b_dcn + oc0);
        float bia1 = __ldg(b_dcn + oc0 + 1);
#pragma unroll
        for (int pxt = 0; pxt < 4; pxt++) {
            int p0 = g_px0 + pxt * 16 + g;
#pragma unroll
            for (int rr = 0; rr < 2; rr++) {
                int p  = p0 + 8 * rr;
                int ho = ho0 + (p >> 7);
                int wo = p & 127;
                out[(((size_t)b * O_ + oc0)     * H_ + ho) * W_ + wo] =
                    acc[pxt][oct][2 * rr + 0] + bia0;
                out[(((size_t)b * O_ + oc0 + 1) * H_ + ho) * W_ + wo] =
                    acc[pxt][oct][2 * rr + 1] + bia1;
            }
        }
    }
}

// ---------------------------------------------------------------------------
extern "C" void kernel_launch(void* const* d_in, const int* in_sizes, int n_in,
                              void* d_out, int out_size)
{
    const float* x     = (const float*)d_in[0];
    const float* w_off = (const float*)d_in[1];
    const float* b_off = (const float*)d_in[2];
    const float* w_dcn = (const float*)d_in[3];
    const float* b_dcn = (const float*)d_in[4];
    float* out = (float*)d_out;

    prep_w_kernel<<<(NDCN + NOFFW + 255) / 256, 256>>>(w_dcn, w_off);
    offset_conv_kernel<<<dim3(H_ / 2, B_), 256>>>(x, b_off);
    deform_kernel<<<dim3(H_ / 2, B_), 256>>>(x, b_dcn, out);
}

// round 11
// speedup vs baseline: 2.3816x; 1.0035x over previous
#include <cuda_runtime.h>
#include <cuda_bf16.h>
#include <cstdint>

#define B_   4
#define C_   64
#define H_   128
#define W_   128
#define O_   64
#define K2C  9
#define OFFC 18
#define NOFF 24   // padded offset-channel count for MMA
#define HW   (H_*W_)

__device__ __align__(16) uint32_t g_wq_hi[K2C * 4 * O_ * 8];  // dcn w [k2][q][o][cp]
__device__ __align__(16) uint32_t g_wq_lo[K2C * 4 * O_ * 8];
__device__ __align__(16) uint32_t g_wo_hi[K2C * 4 * NOFF * 8];// off w [k2][q][o][cp]
__device__ __align__(16) uint32_t g_wo_lo[K2C * 4 * NOFF * 8];

// ---- bf16 warp MMA (m16n8k16, fp32 accum) ----------------------------------
__device__ __forceinline__ void mma_bf16(float* d, const uint32_t* a,
                                         const uint32_t* b) {
    asm volatile(
        "mma.sync.aligned.m16n8k16.row.col.f32.bf16.bf16.f32 "
        "{%0,%1,%2,%3}, {%4,%5,%6,%7}, {%8,%9}, {%0,%1,%2,%3};"
        : "+f"(d[0]), "+f"(d[1]), "+f"(d[2]), "+f"(d[3])
        : "r"(a[0]), "r"(a[1]), "r"(a[2]), "r"(a[3]),
          "r"(b[0]), "r"(b[1]));
}

__device__ __forceinline__ void split_store(uint32_t* hi, uint32_t* lo,
                                            float s0, float s1) {
    float2 sv = make_float2(s0, s1);
    __nv_bfloat162 h2 = __float22bfloat162_rn(sv);
    float2 hv = make_float2(__bfloat162float(h2.x), __bfloat162float(h2.y));
    __nv_bfloat162 l2 = __float22bfloat162_rn(make_float2(sv.x - hv.x, sv.y - hv.y));
    *hi = *reinterpret_cast<uint32_t*>(&h2);
    *lo = *reinterpret_cast<uint32_t*>(&l2);
}

// ---------------------------------------------------------------------------
// Kernel 1: prep both weight tensors (bf16 hi/lo split, [k2][q][o][chpair]).
// ---------------------------------------------------------------------------
#define NDCN (K2C * 4 * O_ * 8)
#define NOFFW (K2C * 4 * NOFF * 8)

__global__ void prep_w_kernel(const float* __restrict__ w_dcn,
                              const float* __restrict__ w_off)
{
    int i = blockIdx.x * 256 + threadIdx.x;
    if (i < NDCN) {
        int k2 = i / (4 * O_ * 8);
        int r  = i % (4 * O_ * 8);
        int q  = r / (O_ * 8);
        int r2 = r % (O_ * 8);
        int o  = r2 / 8;
        int cp = r2 % 8;
        int c  = q * 16 + cp * 2;
        float w0 = w_dcn[(o * C_ + c) * K2C + k2];
        float w1 = w_dcn[(o * C_ + c + 1) * K2C + k2];
        split_store(&g_wq_hi[i], &g_wq_lo[i], w0, w1);
    } else {
        int j = i - NDCN;
        if (j < NOFFW) {
            int k2 = j / (4 * NOFF * 8);
            int r  = j % (4 * NOFF * 8);
            int q  = r / (NOFF * 8);
            int r2 = r % (NOFF * 8);
            int o  = r2 / 8;
            int cp = r2 % 8;
            int c  = q * 16 + cp * 2;
            float w0 = 0.f, w1 = 0.f;
            if (o < OFFC) {
                w0 = w_off[(o * C_ + c) * K2C + k2];
                w1 = w_off[(o * C_ + c + 1) * K2C + k2];
            }
            split_store(&g_wo_hi[j], &g_wo_lo[j], w0, w1);
        }
    }
}

// ---------------------------------------------------------------------------
// Kernel 2: FUSED offset-conv + deformable conv.
// Block = 256 px (2 rows), 256 threads, 2 blocks/SM.
// Phase A: offset conv as 3-split bf16 implicit GEMM (36 iters, 32px x 24oc
//   per warp); offsets land in smem off_s[18][256] — never touch DRAM.
// Phase B: deform as 3-split bf16 implicit GEMM (36 iters, 64px x 32oc per
//   warp); bilinear meta computed ONCE PER TAP into registers (weights +
//   corner offsets for the thread's 2 sampling pixels), offsets read from
//   off_s via conflict-free LDS.
// ---------------------------------------------------------------------------
__global__ void __launch_bounds__(256, 2) fused_kernel(
    const float* __restrict__ x,
    const float* __restrict__ b_off,
    const float* __restrict__ b_dcn,
    float* __restrict__ out)
{
    __shared__ __align__(16) uint32_t smp[2][2][256][9];   // 73.7 KB
    __shared__ __align__(16) uint32_t wsm[2][2][O_][10];   // 20.5 KB
    __shared__ float off_s[OFFC][256];                     // 18 KB

    const int t    = threadIdx.x;
    const int lane = t & 31;
    const int warp = t >> 5;
    const int s_pxg = warp >> 1;          // 64-px group (sampling)
    const int s_cg  = warp & 1;           // 8-ch subgroup (sampling)
    const int ho0   = blockIdx.x * 2;
    const int b     = blockIdx.y;
    const int g  = lane >> 2;
    const int tt = lane & 3;

    const float* xb = x + (size_t)b * C_ * HW;

    // ======================= PHASE A: offset conv ==========================
    {
        const int px0 = warp * 32;        // GEMM: 32 px per warp

        auto stage_wo = [&](int buf, int tap, int q) {
            if (t < 192) {
                int h = t >= 96;
                int r = t - h * 96;
                int o = r >> 2, s = r & 3;
                const uint2* src = (const uint2*)((h ? g_wo_lo : g_wo_hi)
                                   + (size_t)((tap * 4 + q) * NOFF * 8));
                uint2 v = __ldg(src + o * 4 + s);
                *(uint2*)&wsm[buf][h][o][2 * s] = v;
            }
        };

        auto sample_o = [&](int buf, int tap, int q) {
            const int dy = tap / 3 - 1, dx = tap % 3 - 1;
            const int cbase = q * 16 + s_cg * 8;
#pragma unroll
            for (int i = 0; i < 2; i++) {
                int p  = 64 * s_pxg + lane + 32 * i;
                int ho = ho0 + (p >> 7);
                int wo = p & 127;
                int yy = ho + dy, xx = wo + dx;
                bool v = (yy >= 0) & (yy < H_) & (xx >= 0) & (xx < W_);
                int off = yy * W_ + xx;
#pragma unroll
                for (int pr = 0; pr < 4; pr++) {
                    int c0 = cbase + 2 * pr;
                    float s0 = v ? __ldg(xb + (size_t)c0 * HW + off) : 0.f;
                    float s1 = v ? __ldg(xb + (size_t)(c0 + 1) * HW + off) : 0.f;
                    split_store(&smp[buf][0][p][s_cg * 4 + pr],
                                &smp[buf][1][p][s_cg * 4 + pr], s0, s1);
                }
            }
        };

        float acc[2][3][4];
#pragma unroll
        for (int i = 0; i < 2; i++)
#pragma unroll
            for (int j = 0; j < 3; j++)
#pragma unroll
                for (int k = 0; k < 4; k++) acc[i][j][k] = 0.f;

        stage_wo(0, 0, 0);
        sample_o(0, 0, 0);
        __syncthreads();

        for (int it = 0; it < 36; it++) {
            const int buf = it & 1;
            if (it < 35) {
                int n = it + 1;
                stage_wo(n & 1, n >> 2, n & 3);
                sample_o(n & 1, n >> 2, n & 3);
            }
            {
                const uint32_t (*sh)[9]  = smp[buf][0];
                const uint32_t (*sl)[9]  = smp[buf][1];
                const uint32_t (*wh)[10] = wsm[buf][0];
                const uint32_t (*wl)[10] = wsm[buf][1];

                uint32_t bh[3][2], bl[3][2];
#pragma unroll
                for (int oct = 0; oct < 3; oct++) {
                    int orow = oct * 8 + g;
                    bh[oct][0] = wh[orow][tt];
                    bh[oct][1] = wh[orow][tt + 4];
                    bl[oct][0] = wl[orow][tt];
                    bl[oct][1] = wl[orow][tt + 4];
                }
#pragma unroll
                for (int pxt = 0; pxt < 2; pxt++) {
                    int r0 = px0 + pxt * 16 + g;
                    int r1 = r0 + 8;
                    uint32_t ah[4] = { sh[r0][tt], sh[r1][tt],
                                       sh[r0][tt + 4], sh[r1][tt + 4] };
                    uint32_t al[4] = { sl[r0][tt], sl[r1][tt],
                                       sl[r0][tt + 4], sl[r1][tt + 4] };
#pragma unroll
                    for (int oct = 0; oct < 3; oct++) {
                        mma_bf16(acc[pxt][oct], ah, bh[oct]);
                        mma_bf16(acc[pxt][oct], ah, bl[oct]);
                        mma_bf16(acc[pxt][oct], al, bh[oct]);
                    }
                }
            }
            __syncthreads();
        }

        // epilogue -> smem offsets
#pragma unroll
        for (int oct = 0; oct < 3; oct++) {
            int oc0 = oct * 8 + 2 * tt;
            if (oc0 < OFFC) {
                float bia0 = __ldg(b_off + oc0);
                float bia1 = (oc0 + 1 < OFFC) ? __ldg(b_off + oc0 + 1) : 0.f;
#pragma unroll
                for (int pxt = 0; pxt < 2; pxt++) {
#pragma unroll
                    for (int rr = 0; rr < 2; rr++) {
                        int p = px0 + pxt * 16 + g + 8 * rr;
                        off_s[oc0][p] = acc[pxt][oct][2 * rr + 0] + bia0;
                        if (oc0 + 1 < OFFC)
                            off_s[oc0 + 1][p] = acc[pxt][oct][2 * rr + 1] + bia1;
                    }
                }
            }
        }
    }
    __syncthreads();

    // ======================= PHASE B: deformable conv ======================
    {
        const int g_px0 = 64 * (warp >> 1);
        const int g_ob  = 32 * (warp & 1);

        auto stage_wd = [&](int buf, int tap, int q) {
            const uint2* srch = (const uint2*)(g_wq_hi + (size_t)((tap * 4 + q) * O_ * 8));
            const uint2* srcl = (const uint2*)(g_wq_lo + (size_t)((tap * 4 + q) * O_ * 8));
            int o = t >> 2, s = t & 3;
            uint2 vh = __ldg(srch + o * 4 + s);
            uint2 vl = __ldg(srcl + o * 4 + s);
            *(uint2*)&wsm[buf][0][o][2 * s] = vh;
            *(uint2*)&wsm[buf][1][o][2 * s] = vl;
        };

        // per-tap bilinear meta, cached in registers for this thread's 2 px
        float4 mw[2];
        int4   mo[2];

        auto compute_meta = [&](int tap) {
#pragma unroll
            for (int i = 0; i < 2; i++) {
                int p  = 64 * s_pxg + lane + 32 * i;
                int ho = ho0 + (p >> 7);
                int wo = p & 127;
                float oy = off_s[2 * tap][p];
                float ox = off_s[2 * tap + 1][p];
                float py = (float)(ho - 1 + tap / 3) + oy;
                float px = (float)(wo - 1 + tap % 3) + ox;
                float y0f = floorf(py), x0f = floorf(px);
                float wy = py - y0f, wx = px - x0f;
                int y0 = (int)y0f, x0 = (int)x0f;
                float vy0 = ((y0 >= 0)  & (y0 < H_))     ? 1.f : 0.f;
                float vy1 = ((y0 >= -1) & (y0 < H_ - 1)) ? 1.f : 0.f;
                float vx0 = ((x0 >= 0)  & (x0 < W_))     ? 1.f : 0.f;
                float vx1 = ((x0 >= -1) & (x0 < W_ - 1)) ? 1.f : 0.f;
                mw[i].x = (1.f - wy) * (1.f - wx) * vy0 * vx0;
                mw[i].y = (1.f - wy) * wx         * vy0 * vx1;
                mw[i].z = wy * (1.f - wx)         * vy1 * vx0;
                mw[i].w = wy * wx                 * vy1 * vx1;
                int y0c = min(max(y0, 0), H_ - 1);
                int y1c = min(max(y0 + 1, 0), H_ - 1);
                int x0c = min(max(x0, 0), W_ - 1);
                int x1c = min(max(x0 + 1, 0), W_ - 1);
                mo[i].x = y0c * W_ + x0c;
                mo[i].y = y0c * W_ + x1c;
                mo[i].z = y1c * W_ + x0c;
                mo[i].w = y1c * W_ + x1c;
            }
        };

        auto sample_d = [&](int buf, int q) {
            const int cbase = q * 16 + s_cg * 8;
#pragma unroll
            for (int i = 0; i < 2; i++) {
                int p = 64 * s_pxg + lane + 32 * i;
#pragma unroll
                for (int pr = 0; pr < 4; pr++) {
                    int c0 = cbase + 2 * pr;
                    const float* xc0 = xb + c0 * HW;
                    const float* xc1 = xc0 + HW;
                    float s0 = __ldg(xc0 + mo[i].x) * mw[i].x
                             + __ldg(xc0 + mo[i].y) * mw[i].y
                             + __ldg(xc0 + mo[i].z) * mw[i].z
                             + __ldg(xc0 + mo[i].w) * mw[i].w;
                    float s1 = __ldg(xc1 + mo[i].x) * mw[i].x
                             + __ldg(xc1 + mo[i].y) * mw[i].y
                             + __ldg(xc1 + mo[i].z) * mw[i].z
                             + __ldg(xc1 + mo[i].w) * mw[i].w;
                    split_store(&smp[buf][0][p][s_cg * 4 + pr],
                                &smp[buf][1][p][s_cg * 4 + pr], s0, s1);
                }
            }
        };

        float acc[4][4][4];
#pragma unroll
        for (int i = 0; i < 4; i++)
#pragma unroll
            for (int j = 0; j < 4; j++)
#pragma unroll
                for (int k = 0; k < 4; k++) acc[i][j][k] = 0.f;

        stage_wd(0, 0, 0);
        compute_meta(0);
        sample_d(0, 0);
        __syncthreads();

        for (int it = 0; it < 36; it++) {
            const int buf = it & 1;
            if (it < 35) {
                int n = it + 1;
                stage_wd(n & 1, n >> 2, n & 3);
                if ((n & 3) == 0) compute_meta(n >> 2);
                sample_d(n & 1, n & 3);
            }
            {
                const uint32_t (*sh)[9]  = smp[buf][0];
                const uint32_t (*sl)[9]  = smp[buf][1];
                const uint32_t (*wh)[10] = wsm[buf][0];
                const uint32_t (*wl)[10] = wsm[buf][1];

                uint32_t bh[4][2], bl[4][2];
#pragma unroll
                for (int oct = 0; oct < 4; oct++) {
                    int orow = g_ob + oct * 8 + g;
                    bh[oct][0] = wh[orow][tt];
                    bh[oct][1] = wh[orow][tt + 4];
                    bl[oct][0] = wl[orow][tt];
                    bl[oct][1] = wl[orow][tt + 4];
                }
#pragma unroll
                for (int pxt = 0; pxt < 4; pxt++) {
                    int r0 = g_px0 + pxt * 16 + g;
                    int r1 = r0 + 8;
                    uint32_t ah[4] = { sh[r0][tt], sh[r1][tt],
                                       sh[r0][tt + 4], sh[r1][tt + 4] };
                    uint32_t al[4] = { sl[r0][tt], sl[r1][tt],
                                       sl[r0][tt + 4], sl[r1][tt + 4] };
#pragma unroll
                    for (int oct = 0; oct < 4; oct++) {
                        mma_bf16(acc[pxt][oct], ah, bh[oct]);
                        mma_bf16(acc[pxt][oct], ah, bl[oct]);
                        mma_bf16(acc[pxt][oct], al, bh[oct]);
                    }
                }
            }
            __syncthreads();
        }

#pragma unroll
        for (int oct = 0; oct < 4; oct++) {
            int oc0 = g_ob + oct * 8 + 2 * tt;
            float bia0 = __ldg(b_dcn + oc0);
            float bia1 = __ldg(b_dcn + oc0 + 1);
#pragma unroll
            for (int pxt = 0; pxt < 4; pxt++) {
                int p0 = g_px0 + pxt * 16 + g;
#pragma unroll
                for (int rr = 0; rr < 2; rr++) {
                    int p  = p0 + 8 * rr;
                    int ho = ho0 + (p >> 7);
                    int wo = p & 127;
                    out[(((size_t)b * O_ + oc0)     * H_ + ho) * W_ + wo] =
                        acc[pxt][oct][2 * rr + 0] + bia0;
                    out[(((size_t)b * O_ + oc0 + 1) * H_ + ho) * W_ + wo] =
                        acc[pxt][oct][2 * rr + 1] + bia1;
                }
            }
        }
    }
}

// ---------------------------------------------------------------------------
extern "C" void kernel_launch(void* const* d_in, const int* in_sizes, int n_in,
                              void* d_out, int out_size)
{
    const float* x     = (const float*)d_in[0];
    const float* w_off = (const float*)d_in[1];
    const float* b_off = (const float*)d_in[2];
    const float* w_dcn = (const float*)d_in[3];
    const float* b_dcn = (const float*)d_in[4];
    float* out = (float*)d_out;

    prep_w_kernel<<<(NDCN + NOFFW + 255) / 256, 256>>>(w_dcn, w_off);
    fused_kernel<<<dim3(H_ / 2, B_), 256>>>(x, b_off, b_dcn, out);
}